// round 10
// baseline (speedup 1.0000x reference)
#include <cuda_runtime.h>
#include <cuda_fp16.h>

#define DIM 64
#define DIM2 (DIM / 2)
#define N_LAYERS 3
#define NODES_MAX 262144
#define EDGES_MAX 16000000
#define SCAN_BLK 1024
#define PARTS_MAX 256      // NODES_MAX / SCAN_BLK

// -------- static device scratch (no allocations allowed) --------
// Referenced ONLY from device code (host-side symbol decay = ATS-backed
// host shadow on GB300 — the silent R2-R4 bug).
__device__ int     g_is64;
__device__ int     g_counts [NODES_MAX];
__device__ int     g_part   [PARTS_MAX];
__device__ int     g_offsets[NODES_MAX + 1];
__device__ int     g_cursor [NODES_MAX];
__device__ int     g_flag   [NODES_MAX];          // 1 if node queried by dot
__device__ int2    g_csr    [EDGES_MAX];          // (src, val-bits) grouped by dst
__device__ __half2 h_bufA   [NODES_MAX * DIM2];   // e0 -> layer-2 output
__device__ __half2 h_bufB   [NODES_MAX * DIM2];   // layer-1 output
__device__ float   g_l3     [NODES_MAX * DIM];    // layer-3 output (flagged rows)

// -------- index loads: int32 or int64; _cs = streaming (evict-first) --------
__device__ __forceinline__ int load_idx_cs(const void* p, int i, bool is64) {
    if (is64) return (int)__ldcs((const long long*)p + i);
    return __ldcs((const int*)p + i);
}
__device__ __forceinline__ int load_idx(const void* p, int i, bool is64) {
    if (is64) return (int)((const long long*)p)[i];
    return ((const int*)p)[i];
}

// -------- dtype detection: odd 32-bit words all zero => int64 --------
__global__ void detect_kernel(const unsigned int* __restrict__ p, int nslots) {
    __shared__ unsigned int acc;
    if (threadIdx.x == 0) acc = 0u;
    __syncthreads();
    unsigned int v = 0u;
    for (int s = threadIdx.x; s < nslots; s += 1024) v |= p[2 * s + 1];
    if (v) atomicOr(&acc, 1u);
    __syncthreads();
    if (threadIdx.x == 0) g_is64 = (acc == 0u) ? 1 : 0;
}

// -------- init: h_bufA = fp16(emb); counts = flag = 0 --------
__global__ void init_kernel(const float* __restrict__ ue, const float* __restrict__ ie,
                            int nU2, int nT2, int n_nodes) {
    int i = blockIdx.x * blockDim.x + threadIdx.x;   // float2 index
    if (i < nT2) {
        float2 v = (i < nU2) ? ((const float2*)ue)[i] : ((const float2*)ie)[i - nU2];
        h_bufA[i] = __floats2half2_rn(v.x, v.y);
    }
    if (i < n_nodes) { g_counts[i] = 0; g_flag[i] = 0; }
}

// -------- flag queried nodes --------
__global__ void flag_kernel(const void* __restrict__ users, const void* __restrict__ items,
                            int B, int n_users) {
    const bool is64 = (g_is64 != 0);
    int i = blockIdx.x * blockDim.x + threadIdx.x;
    if (i < B) {
        g_flag[load_idx(users, i, is64)] = 1;
        g_flag[n_users + load_idx(items, i, is64)] = 1;
    }
}

// -------- histogram of destinations (streaming edge reads) --------
__global__ void hist_kernel(const void* __restrict__ dst, int n_edges) {
    const bool is64 = (g_is64 != 0);
    int stride = gridDim.x * blockDim.x;
    for (int e = blockIdx.x * blockDim.x + threadIdx.x; e < n_edges; e += stride)
        atomicAdd(&g_counts[load_idx_cs(dst, e, is64)], 1);
}

// ======== 3-phase parallel exclusive scan ========
__global__ void __launch_bounds__(SCAN_BLK)
scan_blocks_kernel(int n_nodes) {
    __shared__ int warp_tot[32];
    int tid  = threadIdx.x;
    int lane = tid & 31, wid = tid >> 5;
    int i = blockIdx.x * SCAN_BLK + tid;
    int v = (i < n_nodes) ? g_counts[i] : 0;

    int x = v;
    #pragma unroll
    for (int o = 1; o < 32; o <<= 1) {
        int t = __shfl_up_sync(0xffffffffu, x, o);
        if (lane >= o) x += t;
    }
    if (lane == 31) warp_tot[wid] = x;
    __syncthreads();
    if (wid == 0) {
        int w = warp_tot[lane];
        #pragma unroll
        for (int o = 1; o < 32; o <<= 1) {
            int t = __shfl_up_sync(0xffffffffu, w, o);
            if (lane >= o) w += t;
        }
        warp_tot[lane] = w;
    }
    __syncthreads();
    int base = wid ? warp_tot[wid - 1] : 0;
    int incl = base + x;
    if (i < n_nodes) g_counts[i] = incl - v;
    if (tid == SCAN_BLK - 1) g_part[blockIdx.x] = incl;
}

__global__ void __launch_bounds__(PARTS_MAX)
scan_parts_kernel(int nb, int n_nodes) {
    __shared__ int warp_tot[8];
    int tid = threadIdx.x, lane = tid & 31, wid = tid >> 5;
    int v = (tid < nb) ? g_part[tid] : 0;
    int x = v;
    #pragma unroll
    for (int o = 1; o < 32; o <<= 1) {
        int t = __shfl_up_sync(0xffffffffu, x, o);
        if (lane >= o) x += t;
    }
    if (lane == 31) warp_tot[wid] = x;
    __syncthreads();
    if (wid == 0 && lane < 8) {
        int w = warp_tot[lane];
        #pragma unroll
        for (int o = 1; o < 8; o <<= 1) {
            int t = __shfl_up_sync(0xffu, w, o);
            if (lane >= o) w += t;
        }
        warp_tot[lane] = w;
    }
    __syncthreads();
    int base = wid ? warp_tot[wid - 1] : 0;
    int incl = base + x;
    if (tid < nb) g_part[tid] = incl - v;
    if (tid == PARTS_MAX - 1) g_offsets[n_nodes] = incl;
}

__global__ void __launch_bounds__(SCAN_BLK)
scan_add_kernel(int n_nodes) {
    int i = blockIdx.x * SCAN_BLK + threadIdx.x;
    if (i < n_nodes) {
        int o = g_counts[i] + g_part[blockIdx.x];
        g_offsets[i] = o;
        g_cursor [i] = o;
    }
}

// -------- scatter edges into CSR slots (streaming edge reads) --------
__global__ void fill_kernel(const void* __restrict__ src, const void* __restrict__ dst,
                            const float* __restrict__ val, int n_edges) {
    const bool is64 = (g_is64 != 0);
    int stride = gridDim.x * blockDim.x;
    for (int e = blockIdx.x * blockDim.x + threadIdx.x; e < n_edges; e += stride) {
        int d = load_idx_cs(dst, e, is64);
        int pos = atomicAdd(&g_cursor[d], 1);
        g_csr[pos] = make_int2(load_idx_cs(src, e, is64), __float_as_int(__ldcs(val + e)));
    }
}

// -------- SpMM body (R8 shape + edge-batch prefetch) --------
// One warp per dst node; lane owns one __half2 (warp-LDG = one 128B line/row).
// Dual fp32 accumulator chains; next edge batch prefetched before processing
// the current one so the CSR L2 latency overlaps the FMA/shfl body.
__device__ __forceinline__ float2 spmm_row(const __half2* __restrict__ x,
                                           int beg, int end, int lane) {
    float2 s0 = make_float2(0.f, 0.f), s1 = make_float2(0.f, 0.f);
    int e = beg;
    int2 ev = make_int2(0, 0);
    if (e + lane < end) ev = __ldcs(&g_csr[e + lane]);
    while (e + 32 <= end) {
        int2 cur = ev;
        e += 32;
        ev = make_int2(0, 0);
        if (e + lane < end) ev = __ldcs(&g_csr[e + lane]);   // prefetch next batch
        #pragma unroll
        for (int k = 0; k < 32; k += 2) {
            int   sA = __shfl_sync(0xffffffffu, cur.x, k);
            float vA = __int_as_float(__shfl_sync(0xffffffffu, cur.y, k));
            int   sB = __shfl_sync(0xffffffffu, cur.x, k + 1);
            float vB = __int_as_float(__shfl_sync(0xffffffffu, cur.y, k + 1));
            float2 xa = __half22float2(x[sA * DIM2 + lane]);
            float2 xb = __half22float2(x[sB * DIM2 + lane]);
            s0.x += vA * xa.x; s0.y += vA * xa.y;
            s1.x += vB * xb.x; s1.y += vB * xb.y;
        }
    }
    int n = end - e;           // 0..31; ev already holds the partial batch
    for (int k = 0; k < n; k++) {
        int   sN = __shfl_sync(0xffffffffu, ev.x, k);
        float vN = __int_as_float(__shfl_sync(0xffffffffu, ev.y, k));
        float2 xf = __half22float2(x[sN * DIM2 + lane]);
        if (k & 1) { s1.x += vN * xf.x; s1.y += vN * xf.y; }
        else       { s0.x += vN * xf.x; s0.y += vN * xf.y; }
    }
    return make_float2(s0.x + s1.x, s0.y + s1.y);
}

// Layers 1-2: full graph, fp16 -> fp16. sel=0: A->B, sel=1: B->A.
__global__ void __launch_bounds__(256)
spmm_full_kernel(int sel, int n_nodes) {
    const __half2* __restrict__ x = sel ? h_bufB : h_bufA;
    __half2*       __restrict__ y = sel ? h_bufA : h_bufB;
    int warp = (blockIdx.x * blockDim.x + threadIdx.x) >> 5;
    int lane = threadIdx.x & 31;
    if (warp >= n_nodes) return;
    float2 s = spmm_row(x, g_offsets[warp], g_offsets[warp + 1], lane);
    y[(size_t)warp * DIM2 + lane] = __floats2half2_rn(s.x, s.y);
}

// Layer 3: flagged (queried) nodes only, fp16 -> fp32 g_l3.
__global__ void __launch_bounds__(256)
spmm_last_kernel(int n_nodes) {
    int warp = (blockIdx.x * blockDim.x + threadIdx.x) >> 5;
    int lane = threadIdx.x & 31;
    if (warp >= n_nodes) return;
    if (!g_flag[warp]) return;
    float2 s = spmm_row(h_bufA, g_offsets[warp], g_offsets[warp + 1], lane);
    ((float2*)(g_l3 + (size_t)warp * DIM))[lane] = s;
}

// -------- final dot: acc = e0(inputs) + l1(bufB) + l2(bufA) + l3(g_l3) -------
__global__ void dot_kernel(const void* __restrict__ users, const void* __restrict__ items,
                           const float* __restrict__ ue, const float* __restrict__ ie,
                           float* __restrict__ out, int B, int n_users) {
    const bool is64 = (g_is64 != 0);
    int warp = (blockIdx.x * blockDim.x + threadIdx.x) >> 5;
    int lane = threadIdx.x & 31;
    if (warp >= B) return;
    int u  = load_idx(users, warp, is64);
    int ni = n_users + load_idx(items, warp, is64);

    float2 e0u = ((const float2*)ue)[(size_t)u * DIM2 + lane];
    float2 l1u = __half22float2(h_bufB[(size_t)u * DIM2 + lane]);
    float2 l2u = __half22float2(h_bufA[(size_t)u * DIM2 + lane]);
    float2 l3u = ((const float2*)(g_l3 + (size_t)u * DIM))[lane];
    float ax = e0u.x + l1u.x + l2u.x + l3u.x;
    float ay = e0u.y + l1u.y + l2u.y + l3u.y;

    float2 e0i = ((const float2*)ie)[(size_t)(ni - n_users) * DIM2 + lane];
    float2 l1i = __half22float2(h_bufB[(size_t)ni * DIM2 + lane]);
    float2 l2i = __half22float2(h_bufA[(size_t)ni * DIM2 + lane]);
    float2 l3i = ((const float2*)(g_l3 + (size_t)ni * DIM))[lane];
    float bx = e0i.x + l1i.x + l2i.x + l3i.x;
    float by = e0i.y + l1i.y + l2i.y + l3i.y;

    float p = ax * bx + ay * by;
    #pragma unroll
    for (int off = 16; off > 0; off >>= 1)
        p += __shfl_xor_sync(0xffffffffu, p, off);
    if (lane == 0) out[warp] = p * (1.0f / ((N_LAYERS + 1) * (N_LAYERS + 1)));
}

extern "C" void kernel_launch(void* const* d_in, const int* in_sizes, int n_in,
                              void* d_out, int out_size) {
    // ---- resolve input permutation from size fingerprint ----
    int iu, ii, is, id, iv, iue, iie;
    if ((long long)in_sizes[0] < (long long)in_sizes[2]) {
        iu = 0; ii = 1; is = 2; id = 3; iv = 4; iue = 5; iie = 6;   // dict order
    } else {
        id = 0; is = 1; iv = 2; iie = 3; ii = 4; iue = 5; iu = 6;   // alphabetical
    }
    const void*  users    = d_in[iu];
    const void*  items    = d_in[ii];
    const void*  edge_src = d_in[is];
    const void*  edge_dst = d_in[id];
    const float* edge_val = (const float*)d_in[iv];
    const float* user_emb = (const float*)d_in[iue];
    const float* item_emb = (const float*)d_in[iie];
    float* out = (float*)d_out;

    const int B       = in_sizes[iu];
    const int n_edges = in_sizes[is];
    const int n_users = in_sizes[iue] / DIM;
    const int n_items = in_sizes[iie] / DIM;
    const int n_nodes = n_users + n_items;
    const int nU2 = n_users * DIM / 2;
    const int nT2 = n_nodes * DIM / 2;
    const int nb  = (n_nodes + SCAN_BLK - 1) / SCAN_BLK;   // <= PARTS_MAX

    // dtype detection + init + flags + CSR build
    int nslots = n_edges / 2 < 4096 ? n_edges / 2 : 4096;
    detect_kernel<<<1, 1024>>>((const unsigned int*)edge_src, nslots);
    init_kernel<<<(nT2 + 255) / 256, 256>>>(user_emb, item_emb, nU2, nT2, n_nodes);
    flag_kernel<<<(B + 255) / 256, 256>>>(users, items, B, n_users);
    hist_kernel<<<2048, 256>>>(edge_dst, n_edges);
    scan_blocks_kernel<<<nb, SCAN_BLK>>>(n_nodes);
    scan_parts_kernel<<<1, PARTS_MAX>>>(nb, n_nodes);
    scan_add_kernel<<<nb, SCAN_BLK>>>(n_nodes);
    fill_kernel<<<2048, 256>>>(edge_src, edge_dst, edge_val, n_edges);

    // propagation: layers 1-2 full, layer 3 only queried nodes
    int spmm_grid = (n_nodes * 32 + 255) / 256;
    spmm_full_kernel<<<spmm_grid, 256>>>(0, n_nodes);   // l1: A -> B
    spmm_full_kernel<<<spmm_grid, 256>>>(1, n_nodes);   // l2: B -> A
    spmm_last_kernel<<<spmm_grid, 256>>>(n_nodes);      // l3: A -> g_l3 (flagged)

    // final dots (acc assembled in-kernel)
    dot_kernel<<<(B * 32 + 255) / 256, 256>>>(users, items, user_emb, item_emb,
                                              out, B, n_users);
}

// round 11
// speedup vs baseline: 1.3400x; 1.3400x over previous
#include <cuda_runtime.h>
#include <cuda_fp16.h>

#define DIM 64
#define DIM2 (DIM / 2)
#define N_LAYERS 3
#define NODES_MAX 262144
#define EDGES_MAX 16000000
#define CAP 256            // per-node bucket capacity (lambda<=96 guaranteed by host guard)
#define SCAN_BLK 1024
#define PARTS_MAX 256      // NODES_MAX / SCAN_BLK

// -------- static device scratch (no allocations allowed) --------
// Referenced ONLY from device code (host-side symbol decay = ATS-backed
// host shadow on GB300 — the silent R2-R4 bug).
__device__ int     g_is64;
__device__ int     g_counts [NODES_MAX];
__device__ int     g_part   [PARTS_MAX];
__device__ int     g_offsets[NODES_MAX + 1];
__device__ int     g_cursor [NODES_MAX];
__device__ int     g_flag   [NODES_MAX];            // 1 if node queried by dot
__device__ int2    g_csr    [EDGES_MAX];            // fallback CSR (lambda > 96)
__device__ int2    g_bucket [(size_t)NODES_MAX * CAP];  // bucket CSR (primary path)
__device__ __half2 h_bufA   [NODES_MAX * DIM2];     // e0 -> layer-2 output
__device__ __half2 h_bufB   [NODES_MAX * DIM2];     // layer-1 output
__device__ float   g_l3     [NODES_MAX * DIM];      // layer-3 output (flagged rows)

// -------- index loads: int32 or int64; _cs = streaming (evict-first) --------
__device__ __forceinline__ int load_idx_cs(const void* p, int i, bool is64) {
    if (is64) return (int)__ldcs((const long long*)p + i);
    return __ldcs((const int*)p + i);
}
__device__ __forceinline__ int load_idx(const void* p, int i, bool is64) {
    if (is64) return (int)((const long long*)p)[i];
    return ((const int*)p)[i];
}

// -------- dtype detection: odd 32-bit words all zero => int64 --------
__global__ void detect_kernel(const unsigned int* __restrict__ p, int nslots) {
    __shared__ unsigned int acc;
    if (threadIdx.x == 0) acc = 0u;
    __syncthreads();
    unsigned int v = 0u;
    for (int s = threadIdx.x; s < nslots; s += 1024) v |= p[2 * s + 1];
    if (v) atomicOr(&acc, 1u);
    __syncthreads();
    if (threadIdx.x == 0) g_is64 = (acc == 0u) ? 1 : 0;
}

// -------- init: h_bufA = fp16(emb); counts = flag = 0 --------
__global__ void init_kernel(const float* __restrict__ ue, const float* __restrict__ ie,
                            int nU2, int nT2, int n_nodes) {
    int i = blockIdx.x * blockDim.x + threadIdx.x;   // float2 index
    if (i < nT2) {
        float2 v = (i < nU2) ? ((const float2*)ue)[i] : ((const float2*)ie)[i - nU2];
        h_bufA[i] = __floats2half2_rn(v.x, v.y);
    }
    if (i < n_nodes) { g_counts[i] = 0; g_flag[i] = 0; }
}

// -------- flag queried nodes --------
__global__ void flag_kernel(const void* __restrict__ users, const void* __restrict__ items,
                            int B, int n_users) {
    const bool is64 = (g_is64 != 0);
    int i = blockIdx.x * blockDim.x + threadIdx.x;
    if (i < B) {
        g_flag[load_idx(users, i, is64)] = 1;
        g_flag[n_users + load_idx(items, i, is64)] = 1;
    }
}

// ======== PRIMARY PATH: single-pass bucket fill (no hist, no scan) ========
__global__ void fill_bucket_kernel(const void* __restrict__ src, const void* __restrict__ dst,
                                   const float* __restrict__ val, int n_edges) {
    const bool is64 = (g_is64 != 0);
    int stride = gridDim.x * blockDim.x;
    for (int e = blockIdx.x * blockDim.x + threadIdx.x; e < n_edges; e += stride) {
        int d = load_idx_cs(dst, e, is64);
        int pos = atomicAdd(&g_counts[d], 1);
        g_bucket[(size_t)d * CAP + pos] =
            make_int2(load_idx_cs(src, e, is64), __float_as_int(__ldcs(val + e)));
    }
}

// ======== FALLBACK PATH: hist + 3-phase scan + cursor fill (lambda > 96) ====
__global__ void hist_kernel(const void* __restrict__ dst, int n_edges) {
    const bool is64 = (g_is64 != 0);
    int stride = gridDim.x * blockDim.x;
    for (int e = blockIdx.x * blockDim.x + threadIdx.x; e < n_edges; e += stride)
        atomicAdd(&g_counts[load_idx_cs(dst, e, is64)], 1);
}

__global__ void __launch_bounds__(SCAN_BLK)
scan_blocks_kernel(int n_nodes) {
    __shared__ int warp_tot[32];
    int tid  = threadIdx.x;
    int lane = tid & 31, wid = tid >> 5;
    int i = blockIdx.x * SCAN_BLK + tid;
    int v = (i < n_nodes) ? g_counts[i] : 0;
    int x = v;
    #pragma unroll
    for (int o = 1; o < 32; o <<= 1) {
        int t = __shfl_up_sync(0xffffffffu, x, o);
        if (lane >= o) x += t;
    }
    if (lane == 31) warp_tot[wid] = x;
    __syncthreads();
    if (wid == 0) {
        int w = warp_tot[lane];
        #pragma unroll
        for (int o = 1; o < 32; o <<= 1) {
            int t = __shfl_up_sync(0xffffffffu, w, o);
            if (lane >= o) w += t;
        }
        warp_tot[lane] = w;
    }
    __syncthreads();
    int base = wid ? warp_tot[wid - 1] : 0;
    int incl = base + x;
    if (i < n_nodes) g_counts[i] = incl - v;
    if (tid == SCAN_BLK - 1) g_part[blockIdx.x] = incl;
}

__global__ void __launch_bounds__(PARTS_MAX)
scan_parts_kernel(int nb, int n_nodes) {
    __shared__ int warp_tot[8];
    int tid = threadIdx.x, lane = tid & 31, wid = tid >> 5;
    int v = (tid < nb) ? g_part[tid] : 0;
    int x = v;
    #pragma unroll
    for (int o = 1; o < 32; o <<= 1) {
        int t = __shfl_up_sync(0xffffffffu, x, o);
        if (lane >= o) x += t;
    }
    if (lane == 31) warp_tot[wid] = x;
    __syncthreads();
    if (wid == 0 && lane < 8) {
        int w = warp_tot[lane];
        #pragma unroll
        for (int o = 1; o < 8; o <<= 1) {
            int t = __shfl_up_sync(0xffu, w, o);
            if (lane >= o) w += t;
        }
        warp_tot[lane] = w;
    }
    __syncthreads();
    int base = wid ? warp_tot[wid - 1] : 0;
    int incl = base + x;
    if (tid < nb) g_part[tid] = incl - v;
    if (tid == PARTS_MAX - 1) g_offsets[n_nodes] = incl;
}

__global__ void __launch_bounds__(SCAN_BLK)
scan_add_kernel(int n_nodes) {
    int i = blockIdx.x * SCAN_BLK + threadIdx.x;
    if (i < n_nodes) {
        int o = g_counts[i] + g_part[blockIdx.x];
        g_offsets[i] = o;
        g_cursor [i] = o;
    }
}

__global__ void fill_kernel(const void* __restrict__ src, const void* __restrict__ dst,
                            const float* __restrict__ val, int n_edges) {
    const bool is64 = (g_is64 != 0);
    int stride = gridDim.x * blockDim.x;
    for (int e = blockIdx.x * blockDim.x + threadIdx.x; e < n_edges; e += stride) {
        int d = load_idx_cs(dst, e, is64);
        int pos = atomicAdd(&g_cursor[d], 1);
        g_csr[pos] = make_int2(load_idx_cs(src, e, is64), __float_as_int(__ldcs(val + e)));
    }
}

// -------- SpMM body (exact R8 shape: known-good 529us) --------
// One warp per dst node; lane owns one __half2 (warp-LDG = one 128B line/row).
// Dual fp32 accumulator chains.
__device__ __forceinline__ float2 spmm_row(const int2* __restrict__ ev_base, int cnt,
                                           const __half2* __restrict__ x, int lane) {
    float2 s0 = make_float2(0.f, 0.f), s1 = make_float2(0.f, 0.f);
    int e = 0;
    for (; e + 32 <= cnt; e += 32) {
        int2 ev = __ldcs(&ev_base[e + lane]);
        #pragma unroll
        for (int k = 0; k < 32; k += 2) {
            int   sA = __shfl_sync(0xffffffffu, ev.x, k);
            float vA = __int_as_float(__shfl_sync(0xffffffffu, ev.y, k));
            int   sB = __shfl_sync(0xffffffffu, ev.x, k + 1);
            float vB = __int_as_float(__shfl_sync(0xffffffffu, ev.y, k + 1));
            float2 xa = __half22float2(x[sA * DIM2 + lane]);
            float2 xb = __half22float2(x[sB * DIM2 + lane]);
            s0.x += vA * xa.x; s0.y += vA * xa.y;
            s1.x += vB * xb.x; s1.y += vB * xb.y;
        }
    }
    int n = cnt - e;
    if (n > 0) {
        int2 ev = (lane < n) ? __ldcs(&ev_base[e + lane]) : make_int2(0, 0);
        for (int k = 0; k < n; k++) {
            int   sN = __shfl_sync(0xffffffffu, ev.x, k);
            float vN = __int_as_float(__shfl_sync(0xffffffffu, ev.y, k));
            float2 xf = __half22float2(x[sN * DIM2 + lane]);
            if (k & 1) { s1.x += vN * xf.x; s1.y += vN * xf.y; }
            else       { s0.x += vN * xf.x; s0.y += vN * xf.y; }
        }
    }
    return make_float2(s0.x + s1.x, s0.y + s1.y);
}

__device__ __forceinline__ const int2* edge_base(int node, int use_bucket, int* cnt) {
    if (use_bucket) {
        *cnt = g_counts[node];
        return &g_bucket[(size_t)node * CAP];
    }
    int beg = g_offsets[node];
    *cnt = g_offsets[node + 1] - beg;
    return &g_csr[beg];
}

// Layers 1-2: full graph, fp16 -> fp16. sel=0: A->B, sel=1: B->A.
__global__ void __launch_bounds__(256)
spmm_full_kernel(int sel, int use_bucket, int n_nodes) {
    const __half2* __restrict__ x = sel ? h_bufB : h_bufA;
    __half2*       __restrict__ y = sel ? h_bufA : h_bufB;
    int warp = (blockIdx.x * blockDim.x + threadIdx.x) >> 5;
    int lane = threadIdx.x & 31;
    if (warp >= n_nodes) return;
    int cnt;
    const int2* ev = edge_base(warp, use_bucket, &cnt);
    float2 s = spmm_row(ev, cnt, x, lane);
    y[(size_t)warp * DIM2 + lane] = __floats2half2_rn(s.x, s.y);
}

// Layer 3: flagged (queried) nodes only, fp16 -> fp32 g_l3.
__global__ void __launch_bounds__(256)
spmm_last_kernel(int use_bucket, int n_nodes) {
    int warp = (blockIdx.x * blockDim.x + threadIdx.x) >> 5;
    int lane = threadIdx.x & 31;
    if (warp >= n_nodes) return;
    if (!g_flag[warp]) return;
    int cnt;
    const int2* ev = edge_base(warp, use_bucket, &cnt);
    float2 s = spmm_row(ev, cnt, h_bufA, lane);
    ((float2*)(g_l3 + (size_t)warp * DIM))[lane] = s;
}

// -------- final dot: acc = e0(inputs) + l1(bufB) + l2(bufA) + l3(g_l3) -------
__global__ void dot_kernel(const void* __restrict__ users, const void* __restrict__ items,
                           const float* __restrict__ ue, const float* __restrict__ ie,
                           float* __restrict__ out, int B, int n_users) {
    const bool is64 = (g_is64 != 0);
    int warp = (blockIdx.x * blockDim.x + threadIdx.x) >> 5;
    int lane = threadIdx.x & 31;
    if (warp >= B) return;
    int u  = load_idx(users, warp, is64);
    int ni = n_users + load_idx(items, warp, is64);

    float2 e0u = ((const float2*)ue)[(size_t)u * DIM2 + lane];
    float2 l1u = __half22float2(h_bufB[(size_t)u * DIM2 + lane]);
    float2 l2u = __half22float2(h_bufA[(size_t)u * DIM2 + lane]);
    float2 l3u = ((const float2*)(g_l3 + (size_t)u * DIM))[lane];
    float ax = e0u.x + l1u.x + l2u.x + l3u.x;
    float ay = e0u.y + l1u.y + l2u.y + l3u.y;

    float2 e0i = ((const float2*)ie)[(size_t)(ni - n_users) * DIM2 + lane];
    float2 l1i = __half22float2(h_bufB[(size_t)ni * DIM2 + lane]);
    float2 l2i = __half22float2(h_bufA[(size_t)ni * DIM2 + lane]);
    float2 l3i = ((const float2*)(g_l3 + (size_t)ni * DIM))[lane];
    float bx = e0i.x + l1i.x + l2i.x + l3i.x;
    float by = e0i.y + l1i.y + l2i.y + l3i.y;

    float p = ax * bx + ay * by;
    #pragma unroll
    for (int off = 16; off > 0; off >>= 1)
        p += __shfl_xor_sync(0xffffffffu, p, off);
    if (lane == 0) out[warp] = p * (1.0f / ((N_LAYERS + 1) * (N_LAYERS + 1)));
}

extern "C" void kernel_launch(void* const* d_in, const int* in_sizes, int n_in,
                              void* d_out, int out_size) {
    // ---- resolve input permutation from size fingerprint ----
    int iu, ii, is, id, iv, iue, iie;
    if ((long long)in_sizes[0] < (long long)in_sizes[2]) {
        iu = 0; ii = 1; is = 2; id = 3; iv = 4; iue = 5; iie = 6;   // dict order
    } else {
        id = 0; is = 1; iv = 2; iie = 3; ii = 4; iue = 5; iu = 6;   // alphabetical
    }
    const void*  users    = d_in[iu];
    const void*  items    = d_in[ii];
    const void*  edge_src = d_in[is];
    const void*  edge_dst = d_in[id];
    const float* edge_val = (const float*)d_in[iv];
    const float* user_emb = (const float*)d_in[iue];
    const float* item_emb = (const float*)d_in[iie];
    float* out = (float*)d_out;

    const int B       = in_sizes[iu];
    const int n_edges = in_sizes[is];
    const int n_users = in_sizes[iue] / DIM;
    const int n_items = in_sizes[iie] / DIM;
    const int n_nodes = n_users + n_items;
    const int nU2 = n_users * DIM / 2;
    const int nT2 = n_nodes * DIM / 2;
    const int nb  = (n_nodes + SCAN_BLK - 1) / SCAN_BLK;   // <= PARTS_MAX

    // bucket path is safe when mean degree is far below CAP (tail ~ e^-50)
    const int use_bucket = ((long long)n_edges <= 96LL * n_nodes) ? 1 : 0;

    // dtype detection + init + flags
    int nslots = n_edges / 2 < 4096 ? n_edges / 2 : 4096;
    detect_kernel<<<1, 1024>>>((const unsigned int*)edge_src, nslots);
    init_kernel<<<(nT2 + 255) / 256, 256>>>(user_emb, item_emb, nU2, nT2, n_nodes);
    flag_kernel<<<(B + 255) / 256, 256>>>(users, items, B, n_users);

    if (use_bucket) {
        // single-pass bucket CSR: no hist, no scan
        fill_bucket_kernel<<<2048, 256>>>(edge_src, edge_dst, edge_val, n_edges);
    } else {
        hist_kernel<<<2048, 256>>>(edge_dst, n_edges);
        scan_blocks_kernel<<<nb, SCAN_BLK>>>(n_nodes);
        scan_parts_kernel<<<1, PARTS_MAX>>>(nb, n_nodes);
        scan_add_kernel<<<nb, SCAN_BLK>>>(n_nodes);
        fill_kernel<<<2048, 256>>>(edge_src, edge_dst, edge_val, n_edges);
    }

    // propagation: layers 1-2 full, layer 3 only queried nodes
    int spmm_grid = (n_nodes * 32 + 255) / 256;
    spmm_full_kernel<<<spmm_grid, 256>>>(0, use_bucket, n_nodes);   // l1: A -> B
    spmm_full_kernel<<<spmm_grid, 256>>>(1, use_bucket, n_nodes);   // l2: B -> A
    spmm_last_kernel<<<spmm_grid, 256>>>(use_bucket, n_nodes);      // l3: A -> g_l3

    // final dots (acc assembled in-kernel)
    dot_kernel<<<(B * 32 + 255) / 256, 256>>>(users, items, user_emb, item_emb,
                                              out, B, n_users);
}

// round 12
// speedup vs baseline: 1.3886x; 1.0363x over previous
#include <cuda_runtime.h>
#include <cuda_fp16.h>

#define DIM 64
#define DIM2 (DIM / 2)
#define N_LAYERS 3
#define NODES_MAX 262144
#define EDGES_MAX 16000000
#define SCAN_BLK 1024
#define PARTS_MAX 256      // NODES_MAX / SCAN_BLK

// -------- static device scratch (no allocations allowed) --------
// Referenced ONLY from device code (host-side symbol decay = ATS-backed
// host shadow on GB300 — the silent R2-R4 bug).
__device__ int     g_is64;
__device__ int     g_counts [NODES_MAX];
__device__ int     g_part   [PARTS_MAX];
__device__ int     g_offsets[NODES_MAX + 1];
__device__ int     g_cursor [NODES_MAX];
__device__ int     g_flag   [NODES_MAX];          // 1 if node queried by dot
__device__ int2    g_csr    [EDGES_MAX];          // (src, val-bits) grouped by dst
__device__ __half2 h_bufA   [NODES_MAX * DIM2];   // e0 -> layer-2 output
__device__ __half2 h_bufB   [NODES_MAX * DIM2];   // layer-1 output
__device__ float   g_l3     [NODES_MAX * DIM];    // layer-3 output (flagged rows)

// -------- index loads: int32 or int64 --------
__device__ __forceinline__ int load_idx(const void* p, int i, bool is64) {
    if (is64) return (int)((const long long*)p)[i];
    return ((const int*)p)[i];
}
// 4 consecutive indices starting at 4*q, via 16B vector loads
__device__ __forceinline__ int4 load_idx4(const void* p, int q, bool is64) {
    if (is64) {
        longlong2 a = ((const longlong2*)p)[2 * q];
        longlong2 b = ((const longlong2*)p)[2 * q + 1];
        return make_int4((int)a.x, (int)a.y, (int)b.x, (int)b.y);
    }
    return ((const int4*)p)[q];
}

// -------- dtype detection: odd 32-bit words all zero => int64 --------
__global__ void detect_kernel(const unsigned int* __restrict__ p, int nslots) {
    __shared__ unsigned int acc;
    if (threadIdx.x == 0) acc = 0u;
    __syncthreads();
    unsigned int v = 0u;
    for (int s = threadIdx.x; s < nslots; s += 1024) v |= p[2 * s + 1];
    if (v) atomicOr(&acc, 1u);
    __syncthreads();
    if (threadIdx.x == 0) g_is64 = (acc == 0u) ? 1 : 0;
}

// -------- init: h_bufA = fp16(emb); counts = flag = 0 --------
__global__ void init_kernel(const float* __restrict__ ue, const float* __restrict__ ie,
                            int nU2, int nT2, int n_nodes) {
    int i = blockIdx.x * blockDim.x + threadIdx.x;   // float2 index
    if (i < nT2) {
        float2 v = (i < nU2) ? ((const float2*)ue)[i] : ((const float2*)ie)[i - nU2];
        h_bufA[i] = __floats2half2_rn(v.x, v.y);
    }
    if (i < n_nodes) { g_counts[i] = 0; g_flag[i] = 0; }
}

// -------- flag queried nodes --------
__global__ void flag_kernel(const void* __restrict__ users, const void* __restrict__ items,
                            int B, int n_users) {
    const bool is64 = (g_is64 != 0);
    int i = blockIdx.x * blockDim.x + threadIdx.x;
    if (i < B) {
        g_flag[load_idx(users, i, is64)] = 1;
        g_flag[n_users + load_idx(items, i, is64)] = 1;
    }
}

// -------- histogram of destinations: 4 edges/thread, 16B loads --------
__global__ void hist_kernel(const void* __restrict__ dst, int n_edges) {
    const bool is64 = (g_is64 != 0);
    int nq = n_edges >> 2;
    int stride = gridDim.x * blockDim.x;
    int tid0 = blockIdx.x * blockDim.x + threadIdx.x;
    for (int q = tid0; q < nq; q += stride) {
        int4 d = load_idx4(dst, q, is64);
        atomicAdd(&g_counts[d.x], 1);
        atomicAdd(&g_counts[d.y], 1);
        atomicAdd(&g_counts[d.z], 1);
        atomicAdd(&g_counts[d.w], 1);
    }
    int t0 = nq << 2;
    int r = n_edges - t0;
    if (tid0 < r) atomicAdd(&g_counts[load_idx(dst, t0 + tid0, is64)], 1);
}

// ======== 3-phase parallel exclusive scan ========
__global__ void __launch_bounds__(SCAN_BLK)
scan_blocks_kernel(int n_nodes) {
    __shared__ int warp_tot[32];
    int tid  = threadIdx.x;
    int lane = tid & 31, wid = tid >> 5;
    int i = blockIdx.x * SCAN_BLK + tid;
    int v = (i < n_nodes) ? g_counts[i] : 0;
    int x = v;
    #pragma unroll
    for (int o = 1; o < 32; o <<= 1) {
        int t = __shfl_up_sync(0xffffffffu, x, o);
        if (lane >= o) x += t;
    }
    if (lane == 31) warp_tot[wid] = x;
    __syncthreads();
    if (wid == 0) {
        int w = warp_tot[lane];
        #pragma unroll
        for (int o = 1; o < 32; o <<= 1) {
            int t = __shfl_up_sync(0xffffffffu, w, o);
            if (lane >= o) w += t;
        }
        warp_tot[lane] = w;
    }
    __syncthreads();
    int base = wid ? warp_tot[wid - 1] : 0;
    int incl = base + x;
    if (i < n_nodes) g_counts[i] = incl - v;
    if (tid == SCAN_BLK - 1) g_part[blockIdx.x] = incl;
}

__global__ void __launch_bounds__(PARTS_MAX)
scan_parts_kernel(int nb, int n_nodes) {
    __shared__ int warp_tot[8];
    int tid = threadIdx.x, lane = tid & 31, wid = tid >> 5;
    int v = (tid < nb) ? g_part[tid] : 0;
    int x = v;
    #pragma unroll
    for (int o = 1; o < 32; o <<= 1) {
        int t = __shfl_up_sync(0xffffffffu, x, o);
        if (lane >= o) x += t;
    }
    if (lane == 31) warp_tot[wid] = x;
    __syncthreads();
    if (wid == 0 && lane < 8) {
        int w = warp_tot[lane];
        #pragma unroll
        for (int o = 1; o < 8; o <<= 1) {
            int t = __shfl_up_sync(0xffu, w, o);
            if (lane >= o) w += t;
        }
        warp_tot[lane] = w;
    }
    __syncthreads();
    int base = wid ? warp_tot[wid - 1] : 0;
    int incl = base + x;
    if (tid < nb) g_part[tid] = incl - v;
    if (tid == PARTS_MAX - 1) g_offsets[n_nodes] = incl;
}

__global__ void __launch_bounds__(SCAN_BLK)
scan_add_kernel(int n_nodes) {
    int i = blockIdx.x * SCAN_BLK + threadIdx.x;
    if (i < n_nodes) {
        int o = g_counts[i] + g_part[blockIdx.x];
        g_offsets[i] = o;
        g_cursor [i] = o;
    }
}

// -------- scatter edges into CSR slots: 4 edges/thread, 16B loads --------
__global__ void fill_kernel(const void* __restrict__ src, const void* __restrict__ dst,
                            const float* __restrict__ val, int n_edges) {
    const bool is64 = (g_is64 != 0);
    int nq = n_edges >> 2;
    int stride = gridDim.x * blockDim.x;
    int tid0 = blockIdx.x * blockDim.x + threadIdx.x;
    for (int q = tid0; q < nq; q += stride) {
        int4   d = load_idx4(dst, q, is64);
        int4   s = load_idx4(src, q, is64);
        float4 v = ((const float4*)val)[q];
        int p0 = atomicAdd(&g_cursor[d.x], 1);
        int p1 = atomicAdd(&g_cursor[d.y], 1);
        int p2 = atomicAdd(&g_cursor[d.z], 1);
        int p3 = atomicAdd(&g_cursor[d.w], 1);
        g_csr[p0] = make_int2(s.x, __float_as_int(v.x));
        g_csr[p1] = make_int2(s.y, __float_as_int(v.y));
        g_csr[p2] = make_int2(s.z, __float_as_int(v.z));
        g_csr[p3] = make_int2(s.w, __float_as_int(v.w));
    }
    int t0 = nq << 2;
    int r = n_edges - t0;
    if (tid0 < r) {
        int e = t0 + tid0;
        int d = load_idx(dst, e, is64);
        int pos = atomicAdd(&g_cursor[d], 1);
        g_csr[pos] = make_int2(load_idx(src, e, is64), __float_as_int(val[e]));
    }
}

// -------- SpMM body (exact R8 shape: known-good 529us) --------
// One warp per dst node; lane owns one __half2 (warp-LDG = one 128B line/row).
// Dual fp32 accumulator chains.
__device__ __forceinline__ float2 spmm_row(const __half2* __restrict__ x,
                                           int beg, int end, int lane) {
    float2 s0 = make_float2(0.f, 0.f), s1 = make_float2(0.f, 0.f);
    int e = beg;
    for (; e + 32 <= end; e += 32) {
        int2 ev = g_csr[e + lane];
        #pragma unroll
        for (int k = 0; k < 32; k += 2) {
            int   sA = __shfl_sync(0xffffffffu, ev.x, k);
            float vA = __int_as_float(__shfl_sync(0xffffffffu, ev.y, k));
            int   sB = __shfl_sync(0xffffffffu, ev.x, k + 1);
            float vB = __int_as_float(__shfl_sync(0xffffffffu, ev.y, k + 1));
            float2 xa = __half22float2(x[sA * DIM2 + lane]);
            float2 xb = __half22float2(x[sB * DIM2 + lane]);
            s0.x += vA * xa.x; s0.y += vA * xa.y;
            s1.x += vB * xb.x; s1.y += vB * xb.y;
        }
    }
    int n = end - e;
    if (n > 0) {
        int2 ev = (lane < n) ? g_csr[e + lane] : make_int2(0, 0);
        for (int k = 0; k < n; k++) {
            int   sN = __shfl_sync(0xffffffffu, ev.x, k);
            float vN = __int_as_float(__shfl_sync(0xffffffffu, ev.y, k));
            float2 xf = __half22float2(x[sN * DIM2 + lane]);
            if (k & 1) { s1.x += vN * xf.x; s1.y += vN * xf.y; }
            else       { s0.x += vN * xf.x; s0.y += vN * xf.y; }
        }
    }
    return make_float2(s0.x + s1.x, s0.y + s1.y);
}

// Layers 1-2: full graph, fp16 -> fp16. sel=0: A->B, sel=1: B->A.
__global__ void __launch_bounds__(256)
spmm_full_kernel(int sel, int n_nodes) {
    const __half2* __restrict__ x = sel ? h_bufB : h_bufA;
    __half2*       __restrict__ y = sel ? h_bufA : h_bufB;
    int warp = (blockIdx.x * blockDim.x + threadIdx.x) >> 5;
    int lane = threadIdx.x & 31;
    if (warp >= n_nodes) return;
    float2 s = spmm_row(x, g_offsets[warp], g_offsets[warp + 1], lane);
    y[(size_t)warp * DIM2 + lane] = __floats2half2_rn(s.x, s.y);
}

// Layer 3: flagged (queried) nodes only, fp16 -> fp32 g_l3.
__global__ void __launch_bounds__(256)
spmm_last_kernel(int n_nodes) {
    int warp = (blockIdx.x * blockDim.x + threadIdx.x) >> 5;
    int lane = threadIdx.x & 31;
    if (warp >= n_nodes) return;
    if (!g_flag[warp]) return;
    float2 s = spmm_row(h_bufA, g_offsets[warp], g_offsets[warp + 1], lane);
    ((float2*)(g_l3 + (size_t)warp * DIM))[lane] = s;
}

// -------- final dot: acc = e0(inputs) + l1(bufB) + l2(bufA) + l3(g_l3) -------
__global__ void dot_kernel(const void* __restrict__ users, const void* __restrict__ items,
                           const float* __restrict__ ue, const float* __restrict__ ie,
                           float* __restrict__ out, int B, int n_users) {
    const bool is64 = (g_is64 != 0);
    int warp = (blockIdx.x * blockDim.x + threadIdx.x) >> 5;
    int lane = threadIdx.x & 31;
    if (warp >= B) return;
    int u  = load_idx(users, warp, is64);
    int ni = n_users + load_idx(items, warp, is64);

    float2 e0u = ((const float2*)ue)[(size_t)u * DIM2 + lane];
    float2 l1u = __half22float2(h_bufB[(size_t)u * DIM2 + lane]);
    float2 l2u = __half22float2(h_bufA[(size_t)u * DIM2 + lane]);
    float2 l3u = ((const float2*)(g_l3 + (size_t)u * DIM))[lane];
    float ax = e0u.x + l1u.x + l2u.x + l3u.x;
    float ay = e0u.y + l1u.y + l2u.y + l3u.y;

    float2 e0i = ((const float2*)ie)[(size_t)(ni - n_users) * DIM2 + lane];
    float2 l1i = __half22float2(h_bufB[(size_t)ni * DIM2 + lane]);
    float2 l2i = __half22float2(h_bufA[(size_t)ni * DIM2 + lane]);
    float2 l3i = ((const float2*)(g_l3 + (size_t)ni * DIM))[lane];
    float bx = e0i.x + l1i.x + l2i.x + l3i.x;
    float by = e0i.y + l1i.y + l2i.y + l3i.y;

    float p = ax * bx + ay * by;
    #pragma unroll
    for (int off = 16; off > 0; off >>= 1)
        p += __shfl_xor_sync(0xffffffffu, p, off);
    if (lane == 0) out[warp] = p * (1.0f / ((N_LAYERS + 1) * (N_LAYERS + 1)));
}

extern "C" void kernel_launch(void* const* d_in, const int* in_sizes, int n_in,
                              void* d_out, int out_size) {
    // ---- resolve input permutation from size fingerprint ----
    int iu, ii, is, id, iv, iue, iie;
    if ((long long)in_sizes[0] < (long long)in_sizes[2]) {
        iu = 0; ii = 1; is = 2; id = 3; iv = 4; iue = 5; iie = 6;   // dict order
    } else {
        id = 0; is = 1; iv = 2; iie = 3; ii = 4; iue = 5; iu = 6;   // alphabetical
    }
    const void*  users    = d_in[iu];
    const void*  items    = d_in[ii];
    const void*  edge_src = d_in[is];
    const void*  edge_dst = d_in[id];
    const float* edge_val = (const float*)d_in[iv];
    const float* user_emb = (const float*)d_in[iue];
    const float* item_emb = (const float*)d_in[iie];
    float* out = (float*)d_out;

    const int B       = in_sizes[iu];
    const int n_edges = in_sizes[is];
    const int n_users = in_sizes[iue] / DIM;
    const int n_items = in_sizes[iie] / DIM;
    const int n_nodes = n_users + n_items;
    const int nU2 = n_users * DIM / 2;
    const int nT2 = n_nodes * DIM / 2;
    const int nb  = (n_nodes + SCAN_BLK - 1) / SCAN_BLK;   // <= PARTS_MAX

    // dtype detection + init + flags + CSR build
    int nslots = n_edges / 2 < 4096 ? n_edges / 2 : 4096;
    detect_kernel<<<1, 1024>>>((const unsigned int*)edge_src, nslots);
    init_kernel<<<(nT2 + 255) / 256, 256>>>(user_emb, item_emb, nU2, nT2, n_nodes);
    flag_kernel<<<(B + 255) / 256, 256>>>(users, items, B, n_users);
    hist_kernel<<<2048, 256>>>(edge_dst, n_edges);
    scan_blocks_kernel<<<nb, SCAN_BLK>>>(n_nodes);
    scan_parts_kernel<<<1, PARTS_MAX>>>(nb, n_nodes);
    scan_add_kernel<<<nb, SCAN_BLK>>>(n_nodes);
    fill_kernel<<<2048, 256>>>(edge_src, edge_dst, edge_val, n_edges);

    // propagation: layers 1-2 full, layer 3 only queried nodes
    int spmm_grid = (n_nodes * 32 + 255) / 256;
    spmm_full_kernel<<<spmm_grid, 256>>>(0, n_nodes);   // l1: A -> B
    spmm_full_kernel<<<spmm_grid, 256>>>(1, n_nodes);   // l2: B -> A
    spmm_last_kernel<<<spmm_grid, 256>>>(n_nodes);      // l3: A -> g_l3 (flagged)

    // final dots (acc assembled in-kernel)
    dot_kernel<<<(B * 32 + 255) / 256, 256>>>(users, items, user_emb, item_emb,
                                              out, B, n_users);
}

// round 13
// speedup vs baseline: 1.5345x; 1.1051x over previous
#include <cuda_runtime.h>
#include <cuda_fp16.h>

#define DIM 64
#define DIM2 (DIM / 2)
#define N_LAYERS 3
#define NODES_MAX 262144
#define EDGES_MAX 16000000
#define CAP 96             // bucket capacity: 262144*96*8B = 201MB max, ~115MB live
#define OVF_MAX 1048576    // overflow list capacity
#define SCAN_BLK 1024
#define PARTS_MAX 256      // NODES_MAX / SCAN_BLK

// -------- static device scratch (no allocations allowed) --------
// Referenced ONLY from device code (host-side symbol decay = ATS-backed
// host shadow on GB300 — the silent R2-R4 bug).
__device__ int     g_is64;
__device__ int     g_ovf_n;
__device__ int     g_counts [NODES_MAX];
__device__ int     g_part   [PARTS_MAX];
__device__ int     g_offsets[NODES_MAX + 1];
__device__ int     g_cursor [NODES_MAX];
__device__ int     g_flag   [NODES_MAX];            // 1 if node queried by dot
__device__ int2    g_csr    [EDGES_MAX];            // fallback CSR
__device__ int2    g_bucket [(size_t)NODES_MAX * CAP];  // primary: bucket CSR
__device__ int4    g_ovf    [OVF_MAX];              // (src, dst, val_bits, 0)
__device__ __half2 h_bufA   [NODES_MAX * DIM2];     // e0 -> layer-2 output
__device__ __half2 h_bufB   [NODES_MAX * DIM2];     // layer-1 output
__device__ float   g_l3     [NODES_MAX * DIM];      // layer-3 output (flagged rows)

// -------- index loads: int32 or int64 --------
__device__ __forceinline__ int load_idx(const void* p, int i, bool is64) {
    if (is64) return (int)((const long long*)p)[i];
    return ((const int*)p)[i];
}
__device__ __forceinline__ int4 load_idx4(const void* p, int q, bool is64) {
    if (is64) {
        longlong2 a = ((const longlong2*)p)[2 * q];
        longlong2 b = ((const longlong2*)p)[2 * q + 1];
        return make_int4((int)a.x, (int)a.y, (int)b.x, (int)b.y);
    }
    return ((const int4*)p)[q];
}

// -------- dtype detection: odd 32-bit words all zero => int64 --------
__global__ void detect_kernel(const unsigned int* __restrict__ p, int nslots) {
    __shared__ unsigned int acc;
    if (threadIdx.x == 0) acc = 0u;
    __syncthreads();
    unsigned int v = 0u;
    for (int s = threadIdx.x; s < nslots; s += 1024) v |= p[2 * s + 1];
    if (v) atomicOr(&acc, 1u);
    __syncthreads();
    if (threadIdx.x == 0) g_is64 = (acc == 0u) ? 1 : 0;
}

// -------- init: h_bufA = fp16(emb); counts = flag = 0; ovf_n = 0 --------
__global__ void init_kernel(const float* __restrict__ ue, const float* __restrict__ ie,
                            int nU2, int nT2, int n_nodes) {
    int i = blockIdx.x * blockDim.x + threadIdx.x;   // float2 index
    if (i == 0) g_ovf_n = 0;
    if (i < nT2) {
        float2 v = (i < nU2) ? ((const float2*)ue)[i] : ((const float2*)ie)[i - nU2];
        h_bufA[i] = __floats2half2_rn(v.x, v.y);
    }
    if (i < n_nodes) { g_counts[i] = 0; g_flag[i] = 0; }
}

// -------- flag queried nodes --------
__global__ void flag_kernel(const void* __restrict__ users, const void* __restrict__ items,
                            int B, int n_users) {
    const bool is64 = (g_is64 != 0);
    int i = blockIdx.x * blockDim.x + threadIdx.x;
    if (i < B) {
        g_flag[load_idx(users, i, is64)] = 1;
        g_flag[n_users + load_idx(items, i, is64)] = 1;
    }
}

// ======== PRIMARY PATH: single-pass bucket fill with overflow ========
__device__ __forceinline__ void bucket_put(int d, int s, int vbits) {
    int pos = atomicAdd(&g_counts[d], 1);
    if (pos < CAP) {
        g_bucket[(size_t)d * CAP + pos] = make_int2(s, vbits);
    } else {
        int o = atomicAdd(&g_ovf_n, 1);
        if (o < OVF_MAX) g_ovf[o] = make_int4(s, d, vbits, 0);
    }
}

__global__ void fill_bucket_kernel(const void* __restrict__ src, const void* __restrict__ dst,
                                   const float* __restrict__ val, int n_edges) {
    const bool is64 = (g_is64 != 0);
    int nq = n_edges >> 2;
    int stride = gridDim.x * blockDim.x;
    int tid0 = blockIdx.x * blockDim.x + threadIdx.x;
    for (int q = tid0; q < nq; q += stride) {
        int4   d = load_idx4(dst, q, is64);
        int4   s = load_idx4(src, q, is64);
        float4 v = ((const float4*)val)[q];
        bucket_put(d.x, s.x, __float_as_int(v.x));
        bucket_put(d.y, s.y, __float_as_int(v.y));
        bucket_put(d.z, s.z, __float_as_int(v.z));
        bucket_put(d.w, s.w, __float_as_int(v.w));
    }
    int t0 = nq << 2;
    int r = n_edges - t0;
    if (tid0 < r) {
        int e = t0 + tid0;
        bucket_put(load_idx(dst, e, is64), load_idx(src, e, is64),
                   __float_as_int(val[e]));
    }
}

// Overflow fix-up for layers 1-2: y[d] += v * x[s] (half2 atomics). One warp/edge.
__global__ void ovf_add_kernel(int sel) {
    const __half2* __restrict__ x = sel ? h_bufB : h_bufA;
    __half2*       __restrict__ y = sel ? h_bufA : h_bufB;
    int n = g_ovf_n; if (n > OVF_MAX) n = OVF_MAX;
    int nw = (gridDim.x * blockDim.x) >> 5;
    int w  = (blockIdx.x * blockDim.x + threadIdx.x) >> 5;
    int lane = threadIdx.x & 31;
    for (int i = w; i < n; i += nw) {
        int4 e = g_ovf[i];
        float v = __int_as_float(e.z);
        float2 xf = __half22float2(x[(size_t)e.x * DIM2 + lane]);
        atomicAdd(&y[(size_t)e.y * DIM2 + lane], __floats2half2_rn(v * xf.x, v * xf.y));
    }
}

// Overflow fix-up for layer 3 (flagged dst only): g_l3[d] += v * x[s] (float atomics).
__global__ void ovf_add_l3_kernel() {
    int n = g_ovf_n; if (n > OVF_MAX) n = OVF_MAX;
    int nw = (gridDim.x * blockDim.x) >> 5;
    int w  = (blockIdx.x * blockDim.x + threadIdx.x) >> 5;
    int lane = threadIdx.x & 31;
    for (int i = w; i < n; i += nw) {
        int4 e = g_ovf[i];
        if (!g_flag[e.y]) continue;
        float v = __int_as_float(e.z);
        float2 xf = __half22float2(h_bufA[(size_t)e.x * DIM2 + lane]);
        float* yp = g_l3 + (size_t)e.y * DIM + lane * 2;
        atomicAdd(yp,     v * xf.x);
        atomicAdd(yp + 1, v * xf.y);
    }
}

// ======== FALLBACK PATH: hist + scan + cursor fill (high mean degree) ========
__global__ void hist_kernel(const void* __restrict__ dst, int n_edges) {
    const bool is64 = (g_is64 != 0);
    int nq = n_edges >> 2;
    int stride = gridDim.x * blockDim.x;
    int tid0 = blockIdx.x * blockDim.x + threadIdx.x;
    for (int q = tid0; q < nq; q += stride) {
        int4 d = load_idx4(dst, q, is64);
        atomicAdd(&g_counts[d.x], 1);
        atomicAdd(&g_counts[d.y], 1);
        atomicAdd(&g_counts[d.z], 1);
        atomicAdd(&g_counts[d.w], 1);
    }
    int t0 = nq << 2;
    int r = n_edges - t0;
    if (tid0 < r) atomicAdd(&g_counts[load_idx(dst, t0 + tid0, is64)], 1);
}

__global__ void __launch_bounds__(SCAN_BLK)
scan_blocks_kernel(int n_nodes) {
    __shared__ int warp_tot[32];
    int tid  = threadIdx.x;
    int lane = tid & 31, wid = tid >> 5;
    int i = blockIdx.x * SCAN_BLK + tid;
    int v = (i < n_nodes) ? g_counts[i] : 0;
    int x = v;
    #pragma unroll
    for (int o = 1; o < 32; o <<= 1) {
        int t = __shfl_up_sync(0xffffffffu, x, o);
        if (lane >= o) x += t;
    }
    if (lane == 31) warp_tot[wid] = x;
    __syncthreads();
    if (wid == 0) {
        int w = warp_tot[lane];
        #pragma unroll
        for (int o = 1; o < 32; o <<= 1) {
            int t = __shfl_up_sync(0xffffffffu, w, o);
            if (lane >= o) w += t;
        }
        warp_tot[lane] = w;
    }
    __syncthreads();
    int base = wid ? warp_tot[wid - 1] : 0;
    int incl = base + x;
    if (i < n_nodes) g_counts[i] = incl - v;
    if (tid == SCAN_BLK - 1) g_part[blockIdx.x] = incl;
}

__global__ void __launch_bounds__(PARTS_MAX)
scan_parts_kernel(int nb, int n_nodes) {
    __shared__ int warp_tot[8];
    int tid = threadIdx.x, lane = tid & 31, wid = tid >> 5;
    int v = (tid < nb) ? g_part[tid] : 0;
    int x = v;
    #pragma unroll
    for (int o = 1; o < 32; o <<= 1) {
        int t = __shfl_up_sync(0xffffffffu, x, o);
        if (lane >= o) x += t;
    }
    if (lane == 31) warp_tot[wid] = x;
    __syncthreads();
    if (wid == 0 && lane < 8) {
        int w = warp_tot[lane];
        #pragma unroll
        for (int o = 1; o < 8; o <<= 1) {
            int t = __shfl_up_sync(0xffu, w, o);
            if (lane >= o) w += t;
        }
        warp_tot[lane] = w;
    }
    __syncthreads();
    int base = wid ? warp_tot[wid - 1] : 0;
    int incl = base + x;
    if (tid < nb) g_part[tid] = incl - v;
    if (tid == PARTS_MAX - 1) g_offsets[n_nodes] = incl;
}

__global__ void __launch_bounds__(SCAN_BLK)
scan_add_kernel(int n_nodes) {
    int i = blockIdx.x * SCAN_BLK + threadIdx.x;
    if (i < n_nodes) {
        int o = g_counts[i] + g_part[blockIdx.x];
        g_offsets[i] = o;
        g_cursor [i] = o;
    }
}

__global__ void fill_kernel(const void* __restrict__ src, const void* __restrict__ dst,
                            const float* __restrict__ val, int n_edges) {
    const bool is64 = (g_is64 != 0);
    int nq = n_edges >> 2;
    int stride = gridDim.x * blockDim.x;
    int tid0 = blockIdx.x * blockDim.x + threadIdx.x;
    for (int q = tid0; q < nq; q += stride) {
        int4   d = load_idx4(dst, q, is64);
        int4   s = load_idx4(src, q, is64);
        float4 v = ((const float4*)val)[q];
        int p0 = atomicAdd(&g_cursor[d.x], 1);
        int p1 = atomicAdd(&g_cursor[d.y], 1);
        int p2 = atomicAdd(&g_cursor[d.z], 1);
        int p3 = atomicAdd(&g_cursor[d.w], 1);
        g_csr[p0] = make_int2(s.x, __float_as_int(v.x));
        g_csr[p1] = make_int2(s.y, __float_as_int(v.y));
        g_csr[p2] = make_int2(s.z, __float_as_int(v.z));
        g_csr[p3] = make_int2(s.w, __float_as_int(v.w));
    }
    int t0 = nq << 2;
    int r = n_edges - t0;
    if (tid0 < r) {
        int e = t0 + tid0;
        int d = load_idx(dst, e, is64);
        int pos = atomicAdd(&g_cursor[d], 1);
        g_csr[pos] = make_int2(load_idx(src, e, is64), __float_as_int(val[e]));
    }
}

// -------- SpMM body (exact R8 shape) --------
__device__ __forceinline__ float2 spmm_row(const int2* __restrict__ ev_base, int cnt,
                                           const __half2* __restrict__ x, int lane) {
    float2 s0 = make_float2(0.f, 0.f), s1 = make_float2(0.f, 0.f);
    int e = 0;
    for (; e + 32 <= cnt; e += 32) {
        int2 ev = ev_base[e + lane];
        #pragma unroll
        for (int k = 0; k < 32; k += 2) {
            int   sA = __shfl_sync(0xffffffffu, ev.x, k);
            float vA = __int_as_float(__shfl_sync(0xffffffffu, ev.y, k));
            int   sB = __shfl_sync(0xffffffffu, ev.x, k + 1);
            float vB = __int_as_float(__shfl_sync(0xffffffffu, ev.y, k + 1));
            float2 xa = __half22float2(x[sA * DIM2 + lane]);
            float2 xb = __half22float2(x[sB * DIM2 + lane]);
            s0.x += vA * xa.x; s0.y += vA * xa.y;
            s1.x += vB * xb.x; s1.y += vB * xb.y;
        }
    }
    int n = cnt - e;
    if (n > 0) {
        int2 ev = (lane < n) ? ev_base[e + lane] : make_int2(0, 0);
        for (int k = 0; k < n; k++) {
            int   sN = __shfl_sync(0xffffffffu, ev.x, k);
            float vN = __int_as_float(__shfl_sync(0xffffffffu, ev.y, k));
            float2 xf = __half22float2(x[sN * DIM2 + lane]);
            if (k & 1) { s1.x += vN * xf.x; s1.y += vN * xf.y; }
            else       { s0.x += vN * xf.x; s0.y += vN * xf.y; }
        }
    }
    return make_float2(s0.x + s1.x, s0.y + s1.y);
}

__device__ __forceinline__ const int2* edge_base(int node, int use_bucket, int* cnt) {
    if (use_bucket) {
        int c = g_counts[node];
        *cnt = (c < CAP) ? c : CAP;
        return &g_bucket[(size_t)node * CAP];
    }
    int beg = g_offsets[node];
    *cnt = g_offsets[node + 1] - beg;
    return &g_csr[beg];
}

// Layers 1-2: full graph, fp16 -> fp16. sel=0: A->B, sel=1: B->A.
__global__ void __launch_bounds__(256)
spmm_full_kernel(int sel, int use_bucket, int n_nodes) {
    const __half2* __restrict__ x = sel ? h_bufB : h_bufA;
    __half2*       __restrict__ y = sel ? h_bufA : h_bufB;
    int warp = (blockIdx.x * blockDim.x + threadIdx.x) >> 5;
    int lane = threadIdx.x & 31;
    if (warp >= n_nodes) return;
    int cnt;
    const int2* ev = edge_base(warp, use_bucket, &cnt);
    float2 s = spmm_row(ev, cnt, x, lane);
    y[(size_t)warp * DIM2 + lane] = __floats2half2_rn(s.x, s.y);
}

// Layer 3: flagged (queried) nodes only, fp16 -> fp32 g_l3.
__global__ void __launch_bounds__(256)
spmm_last_kernel(int use_bucket, int n_nodes) {
    int warp = (blockIdx.x * blockDim.x + threadIdx.x) >> 5;
    int lane = threadIdx.x & 31;
    if (warp >= n_nodes) return;
    if (!g_flag[warp]) return;
    int cnt;
    const int2* ev = edge_base(warp, use_bucket, &cnt);
    float2 s = spmm_row(ev, cnt, h_bufA, lane);
    ((float2*)(g_l3 + (size_t)warp * DIM))[lane] = s;
}

// -------- final dot: acc = e0(inputs) + l1(bufB) + l2(bufA) + l3(g_l3) -------
__global__ void dot_kernel(const void* __restrict__ users, const void* __restrict__ items,
                           const float* __restrict__ ue, const float* __restrict__ ie,
                           float* __restrict__ out, int B, int n_users) {
    const bool is64 = (g_is64 != 0);
    int warp = (blockIdx.x * blockDim.x + threadIdx.x) >> 5;
    int lane = threadIdx.x & 31;
    if (warp >= B) return;
    int u  = load_idx(users, warp, is64);
    int ni = n_users + load_idx(items, warp, is64);

    float2 e0u = ((const float2*)ue)[(size_t)u * DIM2 + lane];
    float2 l1u = __half22float2(h_bufB[(size_t)u * DIM2 + lane]);
    float2 l2u = __half22float2(h_bufA[(size_t)u * DIM2 + lane]);
    float2 l3u = ((const float2*)(g_l3 + (size_t)u * DIM))[lane];
    float ax = e0u.x + l1u.x + l2u.x + l3u.x;
    float ay = e0u.y + l1u.y + l2u.y + l3u.y;

    float2 e0i = ((const float2*)ie)[(size_t)(ni - n_users) * DIM2 + lane];
    float2 l1i = __half22float2(h_bufB[(size_t)ni * DIM2 + lane]);
    float2 l2i = __half22float2(h_bufA[(size_t)ni * DIM2 + lane]);
    float2 l3i = ((const float2*)(g_l3 + (size_t)ni * DIM))[lane];
    float bx = e0i.x + l1i.x + l2i.x + l3i.x;
    float by = e0i.y + l1i.y + l2i.y + l3i.y;

    float p = ax * bx + ay * by;
    #pragma unroll
    for (int off = 16; off > 0; off >>= 1)
        p += __shfl_xor_sync(0xffffffffu, p, off);
    if (lane == 0) out[warp] = p * (1.0f / ((N_LAYERS + 1) * (N_LAYERS + 1)));
}

extern "C" void kernel_launch(void* const* d_in, const int* in_sizes, int n_in,
                              void* d_out, int out_size) {
    // ---- resolve input permutation from size fingerprint ----
    int iu, ii, is, id, iv, iue, iie;
    if ((long long)in_sizes[0] < (long long)in_sizes[2]) {
        iu = 0; ii = 1; is = 2; id = 3; iv = 4; iue = 5; iie = 6;   // dict order
    } else {
        id = 0; is = 1; iv = 2; iie = 3; ii = 4; iue = 5; iu = 6;   // alphabetical
    }
    const void*  users    = d_in[iu];
    const void*  items    = d_in[ii];
    const void*  edge_src = d_in[is];
    const void*  edge_dst = d_in[id];
    const float* edge_val = (const float*)d_in[iv];
    const float* user_emb = (const float*)d_in[iue];
    const float* item_emb = (const float*)d_in[iie];
    float* out = (float*)d_out;

    const int B       = in_sizes[iu];
    const int n_edges = in_sizes[is];
    const int n_users = in_sizes[iue] / DIM;
    const int n_items = in_sizes[iie] / DIM;
    const int n_nodes = n_users + n_items;
    const int nU2 = n_users * DIM / 2;
    const int nT2 = n_nodes * DIM / 2;
    const int nb  = (n_nodes + SCAN_BLK - 1) / SCAN_BLK;   // <= PARTS_MAX

    // bucket path when mean degree is comfortably below CAP (overflow handled anyway,
    // but the list must stay small); fallback to full CSR otherwise
    const int use_bucket = ((long long)n_edges <= 80LL * n_nodes) ? 1 : 0;

    // dtype detection + init + flags
    int nslots = n_edges / 2 < 4096 ? n_edges / 2 : 4096;
    detect_kernel<<<1, 1024>>>((const unsigned int*)edge_src, nslots);
    init_kernel<<<(nT2 + 255) / 256, 256>>>(user_emb, item_emb, nU2, nT2, n_nodes);
    flag_kernel<<<(B + 255) / 256, 256>>>(users, items, B, n_users);

    if (use_bucket) {
        fill_bucket_kernel<<<2048, 256>>>(edge_src, edge_dst, edge_val, n_edges);
    } else {
        hist_kernel<<<2048, 256>>>(edge_dst, n_edges);
        scan_blocks_kernel<<<nb, SCAN_BLK>>>(n_nodes);
        scan_parts_kernel<<<1, PARTS_MAX>>>(nb, n_nodes);
        scan_add_kernel<<<nb, SCAN_BLK>>>(n_nodes);
        fill_kernel<<<2048, 256>>>(edge_src, edge_dst, edge_val, n_edges);
    }

    // propagation: layers 1-2 full, layer 3 only queried nodes
    int spmm_grid = (n_nodes * 32 + 255) / 256;
    spmm_full_kernel<<<spmm_grid, 256>>>(0, use_bucket, n_nodes);   // l1: A -> B
    if (use_bucket) ovf_add_kernel<<<16, 256>>>(0);
    spmm_full_kernel<<<spmm_grid, 256>>>(1, use_bucket, n_nodes);   // l2: B -> A
    if (use_bucket) ovf_add_kernel<<<16, 256>>>(1);
    spmm_last_kernel<<<spmm_grid, 256>>>(use_bucket, n_nodes);      // l3: A -> g_l3
    if (use_bucket) ovf_add_l3_kernel<<<16, 256>>>();

    // final dots (acc assembled in-kernel)
    dot_kernel<<<(B * 32 + 255) / 256, 256>>>(users, items, user_emb, item_emb,
                                              out, B, n_users);
}